// round 17
// baseline (speedup 1.0000x reference)
#include <cuda_runtime.h>
#include <cuda_fp16.h>
#include <cstdint>

#define NN 1024
#define DD 32
#define HH 64
#define LN_EPS 1e-5f

typedef unsigned long long ull;

// ---------------- device globals ----------------
__device__ float  g_hs[NN * HH];          // X @ W1[:32] (fp32, for Phase B)
__device__ __half g_hsH[NN * HH];         // fp16 copy for dot GEMM
__device__ __half g_hdH[NN * HH];         // fp16 copy for dot GEMM
__device__ float  g_hsum[NN];             // row sums of hs
__device__ float  g_dsum[NN];             // row sums of hd
__device__ float  g_hs2[NN];              // row sums of hs^2 (fp32 exact)
__device__ float  g_hd2[NN];              // row sums of hd^2 (fp32 exact)
__device__ float  g_q[NN * NN];           // q[i][j] = Shs2[i] + 2*dot + Shd2[j]  (4 MB)
__device__ uint4  g_w2f4[8 * 2 * 32];     // fp16 W2 B-frags: [nt][kp][lane]
__device__ ull    g_hdF[64 * 2 * 8 * 32]; // hd in pair-kernel fragment order

// ---------------- packed f32x2 helpers ----------------
__device__ __forceinline__ ull p2_add(ull a, ull b) {
    ull r; asm("add.rn.f32x2 %0, %1, %2;" : "=l"(r) : "l"(a), "l"(b)); return r;
}
__device__ __forceinline__ ull p2_fma(ull a, ull b, ull c) {
    ull r; asm("fma.rn.f32x2 %0, %1, %2, %3;" : "=l"(r) : "l"(a), "l"(b), "l"(c)); return r;
}
__device__ __forceinline__ ull p2_pack(float lo, float hi) {
    ull r; asm("mov.b64 %0, {%1, %2};" : "=l"(r) : "f"(lo), "f"(hi)); return r;
}
__device__ __forceinline__ void p2_unpack(ull v, float& lo, float& hi) {
    asm("mov.b64 {%0, %1}, %2;" : "=f"(lo), "=f"(hi) : "l"(v));
}
__device__ __forceinline__ uint32_t pack_h2(float a, float b) {
    __half2 t = __floats2half2_rn(a, b);
    return *reinterpret_cast<uint32_t*>(&t);
}
__device__ __forceinline__ void mma_f16(float* c, uint32_t a0, uint32_t a1,
                                        uint32_t a2, uint32_t a3,
                                        uint32_t b0, uint32_t b1) {
    asm volatile(
        "mma.sync.aligned.m16n8k16.row.col.f32.f16.f16.f32 "
        "{%0,%1,%2,%3}, {%4,%5,%6,%7}, {%8,%9}, {%0,%1,%2,%3};"
        : "+f"(c[0]), "+f"(c[1]), "+f"(c[2]), "+f"(c[3])
        : "r"(a0), "r"(a1), "r"(a2), "r"(a3), "r"(b0), "r"(b1));
}
__device__ __forceinline__ float qred(float v) {
    v += __shfl_xor_sync(0xffffffffu, v, 1);
    v += __shfl_xor_sync(0xffffffffu, v, 2);
    return v;
}
__device__ __forceinline__ float wred32(float v) {
    #pragma unroll
    for (int s = 16; s > 0; s >>= 1) v += __shfl_xor_sync(0xffffffffu, v, s);
    return v;
}
__device__ __forceinline__ ull ldg_ull(const float* p) {
    return *reinterpret_cast<const ull*>(p);
}
__device__ __forceinline__ uint32_t ldh2(const __half* p) {
    return *reinterpret_cast<const uint32_t*>(p);
}

// ---------------- fused prep ----------------
__global__ void prep_all(const float* __restrict__ X,
                         const float* __restrict__ W1,
                         const float* __restrict__ b1,
                         const float* __restrict__ W2) {
    if (blockIdx.x < 64) {
        __shared__ float xs[16][DD];
        __shared__ float sh[16][HH];
        __shared__ float sd[16][HH];
        int t = threadIdx.x;
        int blk = blockIdx.x;
        #pragma unroll
        for (int e = 0; e < 2; e++) {
            int idx = t + e * 256;
            int r = idx >> 5, c = idx & 31;
            xs[r][c] = X[(blk * 16 + r) * DD + c];
        }
        __syncthreads();
        int n = t & 63;
        int rg = t >> 6;
        float b1n = b1[n];
        float hsv[4], hdv[4];
        #pragma unroll
        for (int q = 0; q < 4; q++) { hsv[q] = 0.f; hdv[q] = b1n; }
        #pragma unroll
        for (int d = 0; d < DD; d++) {
            float ws = W1[d * HH + n];
            float wd = W1[(DD + d) * HH + n];
            #pragma unroll
            for (int q = 0; q < 4; q++) {
                float xv = xs[rg * 4 + q][d];
                hsv[q] = fmaf(xv, ws, hsv[q]);
                hdv[q] = fmaf(xv, wd, hdv[q]);
            }
        }
        #pragma unroll
        for (int q = 0; q < 4; q++) {
            int r = rg * 4 + q;
            sh[r][n] = hsv[q];
            sd[r][n] = hdv[q];
            g_hs[(blk * 16 + r) * HH + n] = hsv[q];
            g_hsH[(blk * 16 + r) * HH + n] = __float2half_rn(hsv[q]);
            g_hdH[(blk * 16 + r) * HH + n] = __float2half_rn(hdv[q]);
        }
        __syncthreads();
        // 64 concurrent reductions: hsum, dsum, hs2, hd2 (16 rows each)
        int wi = t >> 5, lid = t & 31;
        #pragma unroll
        for (int e = 0; e < 8; e++) {
            int idx = wi + e * 8;                // 0..63
            int which = idx >> 4, row = idx & 15;
            const float* src = (which == 0 || which == 2) ? sh[row] : sd[row];
            float v;
            if (which < 2) v = src[lid] + src[lid + 32];
            else {
                float x1 = src[lid], x2 = src[lid + 32];
                v = x1 * x1 + x2 * x2;
            }
            v = wred32(v);
            if (lid == 0) {
                int gi = blk * 16 + row;
                if      (which == 0) g_hsum[gi] = v;
                else if (which == 1) g_dsum[gi] = v;
                else if (which == 2) g_hs2[gi] = v;
                else                 g_hd2[gi] = v;
            }
        }
        // g_hdF in pair-kernel fragment order (fp32, unchanged)
        #pragma unroll
        for (int e = 0; e < 2; e++) {
            int idx = t + e * 256;
            int lane = idx & 31;
            int ci = (idx >> 5) & 7;
            int rr = idx >> 8;
            int qr2 = lane >> 2, qc2 = lane & 3;
            int row = rr * 8 + qr2;
            int c = (ci >> 1) * 16 + (ci & 1) * 8 + qc2 * 2;
            g_hdF[blk * 512 + idx] = p2_pack(sd[row][c], sd[row][c + 1]);
        }
    } else {
        #pragma unroll
        for (int e = 0; e < 2; e++) {
            int tt = threadIdx.x + e * 256;
            int lane = tt & 31;
            int kp = (tt >> 5) & 1;
            int nt = tt >> 6;
            int n  = nt * 8 + (lane >> 2);
            int kq = kp * 32 + (lane & 3) * 2;
            uint4 r;
            r.x = pack_h2(W2[kq * HH + n],        W2[(kq + 1) * HH + n]);
            r.y = pack_h2(W2[(kq + 8) * HH + n],  W2[(kq + 9) * HH + n]);
            r.z = pack_h2(W2[(kq + 16) * HH + n], W2[(kq + 17) * HH + n]);
            r.w = pack_h2(W2[(kq + 24) * HH + n], W2[(kq + 25) * HH + n]);
            g_w2f4[tt] = r;
        }
    }
}

// ---------------- dot kernel: g_q[i][j] = Shs2[i] + 2*dot(hs_i,hd_j) + Shd2[j] ----------------
// A rows = i (hs), B cols = j (hd); m16n8k16, K=64 in 4 steps.
// CTA: 128 thr / 4 warps; warp w covers i-tile [ (by*4+w)*16, +16 ), j block [bx*64, +64).
__global__ __launch_bounds__(128) void dot_kernel() {
    int tid = threadIdx.x;
    int w = tid >> 5, lane = tid & 31;
    int r = lane >> 2, qcc = lane & 3;
    int ib = (blockIdx.y * 4 + w) * 16;
    int j0 = blockIdx.x * 64;

    float acc[8][4];
    #pragma unroll
    for (int nt = 0; nt < 8; nt++)
        #pragma unroll
        for (int e = 0; e < 4; e++) acc[nt][e] = 0.f;

    #pragma unroll
    for (int kk = 0; kk < 4; kk++) {
        int c0 = kk * 16 + qcc * 2;
        uint32_t a0 = ldh2(g_hsH + (ib + r) * HH + c0);
        uint32_t a1 = ldh2(g_hsH + (ib + r + 8) * HH + c0);
        uint32_t a2 = ldh2(g_hsH + (ib + r) * HH + c0 + 8);
        uint32_t a3 = ldh2(g_hsH + (ib + r + 8) * HH + c0 + 8);
        #pragma unroll
        for (int nt = 0; nt < 8; nt++) {
            int n = j0 + nt * 8 + r;
            uint32_t b0 = ldh2(g_hdH + n * HH + c0);
            uint32_t b1 = ldh2(g_hdH + n * HH + c0 + 8);
            mma_f16(acc[nt], a0, a1, a2, a3, b0, b1);
        }
    }

    float hs2r  = g_hs2[ib + r];
    float hs2r8 = g_hs2[ib + r + 8];
    ull two = p2_pack(2.f, 2.f);
    ull s2a = p2_pack(hs2r, hs2r);
    ull s2b = p2_pack(hs2r8, hs2r8);
    #pragma unroll
    for (int nt = 0; nt < 8; nt++) {
        int j = j0 + nt * 8 + qcc * 2;
        ull h2 = ldg_ull(g_hd2 + j);
        ull qa = p2_fma(p2_pack(acc[nt][0], acc[nt][1]), two, p2_add(s2a, h2));
        ull qb = p2_fma(p2_pack(acc[nt][2], acc[nt][3]), two, p2_add(s2b, h2));
        *reinterpret_cast<ull*>(g_q + (ib + r) * NN + j)     = qa;
        *reinterpret_cast<ull*>(g_q + (ib + r + 8) * NN + j) = qb;
    }
}

// ---------------- main pair kernel: Phase A replaced by q loads ----------------
__global__ __launch_bounds__(128, 4) void pair_kernel(
    const float* __restrict__ g1, const float* __restrict__ be1,
    const float* __restrict__ b2, const float* __restrict__ g2,
    const float* __restrict__ be2, const float* __restrict__ W3,
    const float* __restrict__ b3, float* __restrict__ out) {
    int tid = threadIdx.x;
    int w = tid >> 5, lane = tid & 31;
    int qr = lane >> 2, qc = lane & 3;
    int bx = blockIdx.x, by = blockIdx.y;

    ull dA[8], dB[8];
    {
        const ull* hdF = g_hdF + bx * 512;
        #pragma unroll
        for (int ci = 0; ci < 8; ci++) {
            dA[ci] = hdF[ci * 32 + lane];
            dB[ci] = hdF[256 + ci * 32 + lane];
        }
    }
    const float* hsr0 = g_hs + (by * 8 + w * 2) * HH;
    const float* hsr1 = hsr0 + HH;

    // ---- Phase A (new): q loads + stats (no squares, no shuffles) ----
    int i0 = by * 8 + w * 2;
    int j1 = bx * 16 + qr;
    float q0 = g_q[i0 * NN + j1];
    float q1 = g_q[i0 * NN + j1 + 8];
    float q2 = g_q[(i0 + 1) * NN + j1];
    float q3 = g_q[(i0 + 1) * NN + j1 + 8];
    float Sv0 = g_hsum[i0], Sv1 = g_hsum[i0 + 1];
    float Tv1 = g_dsum[j1], Tv2 = g_dsum[j1 + 8];
    float mu0 = (Sv0 + Tv1) * (1.f / HH);
    float mu1 = (Sv0 + Tv2) * (1.f / HH);
    float mu2 = (Sv1 + Tv1) * (1.f / HH);
    float mu3 = (Sv1 + Tv2) * (1.f / HH);
    float rs0 = rsqrtf(q0 * (1.f / HH) - mu0 * mu0 + LN_EPS);
    float rs1 = rsqrtf(q1 * (1.f / HH) - mu1 * mu1 + LN_EPS);
    float rs2 = rsqrtf(q2 * (1.f / HH) - mu2 * mu2 + LN_EPS);
    float rs3 = rsqrtf(q3 * (1.f / HH) - mu3 * mu3 + LN_EPS);
    ull rsp0 = p2_pack(rs0, rs0), nmp0 = p2_pack(-mu0 * rs0, -mu0 * rs0);
    ull rsp1 = p2_pack(rs1, rs1), nmp1 = p2_pack(-mu1 * rs1, -mu1 * rs1);
    ull rsp2 = p2_pack(rs2, rs2), nmp2 = p2_pack(-mu2 * rs2, -mu2 * rs2);
    ull rsp3 = p2_pack(rs3, rs3), nmp3 = p2_pack(-mu3 * rs3, -mu3 * rs3);

    // ---- Phase B: apply, column-outer ----
    uint32_t af[2][4][4];
    #pragma unroll
    for (int ci = 0; ci < 8; ci++) {
        int kk = ci >> 1, h = ci & 1;
        int c = kk * 16 + h * 8 + qc * 2;
        ull gp = ldg_ull(g1 + c);
        ull bp = ldg_ull(be1 + c);
        ull a0 = ldg_ull(hsr0 + c);
        ull a1 = ldg_ull(hsr1 + c);
        ull x, v;
        float va, vb;
        x = p2_add(a0, dA[ci]);
        v = p2_fma(p2_fma(x, rsp0, nmp0), gp, bp);
        p2_unpack(v, va, vb);
        af[0][kk][h * 2 + 0] = pack_h2(fmaxf(va, 0.f), fmaxf(vb, 0.f));
        x = p2_add(a0, dB[ci]);
        v = p2_fma(p2_fma(x, rsp1, nmp1), gp, bp);
        p2_unpack(v, va, vb);
        af[0][kk][h * 2 + 1] = pack_h2(fmaxf(va, 0.f), fmaxf(vb, 0.f));
        x = p2_add(a1, dA[ci]);
        v = p2_fma(p2_fma(x, rsp2, nmp2), gp, bp);
        p2_unpack(v, va, vb);
        af[1][kk][h * 2 + 0] = pack_h2(fmaxf(va, 0.f), fmaxf(vb, 0.f));
        x = p2_add(a1, dB[ci]);
        v = p2_fma(p2_fma(x, rsp3, nmp3), gp, bp);
        p2_unpack(v, va, vb);
        af[1][kk][h * 2 + 1] = pack_h2(fmaxf(va, 0.f), fmaxf(vb, 0.f));
    }

    // ---- fused MMA, acc initialized with b2 ----
    float acc[2][8][4];
    #pragma unroll
    for (int nt = 0; nt < 8; nt++) {
        int c = nt * 8 + qc * 2;
        ull b2p = ldg_ull(b2 + c);
        float bxv, byv;
        p2_unpack(b2p, bxv, byv);
        #pragma unroll
        for (int mt = 0; mt < 2; mt++) {
            acc[mt][nt][0] = bxv; acc[mt][nt][1] = byv;
            acc[mt][nt][2] = bxv; acc[mt][nt][3] = byv;
        }
    }
    #pragma unroll
    for (int nt = 0; nt < 8; nt++) {
        #pragma unroll
        for (int kp = 0; kp < 2; kp++) {
            uint4 B = g_w2f4[(nt * 2 + kp) * 32 + lane];
            int k0 = 2 * kp, k1 = 2 * kp + 1;
            mma_f16(acc[0][nt], af[0][k0][0], af[0][k0][1], af[0][k0][2], af[0][k0][3], B.x, B.y);
            mma_f16(acc[1][nt], af[1][k0][0], af[1][k0][1], af[1][k0][2], af[1][k0][3], B.x, B.y);
            mma_f16(acc[0][nt], af[0][k1][0], af[0][k1][1], af[0][k1][2], af[0][k1][3], B.z, B.w);
            mma_f16(acc[1][nt], af[1][k1][0], af[1][k1][1], af[1][k1][2], af[1][k1][3], B.z, B.w);
        }
    }

    // ---- Epilogue Phase A ----
    float lo, hi;
    ull ts[2][2][2];
    #pragma unroll
    for (int mt = 0; mt < 2; mt++) {
        ull t0 = 0ull, t1 = 0ull, t2 = 0ull, t3 = 0ull;
        #pragma unroll
        for (int nt = 0; nt < 8; nt++) {
            ull ua = p2_pack(acc[mt][nt][0], acc[mt][nt][1]);
            ull ub = p2_pack(acc[mt][nt][2], acc[mt][nt][3]);
            t0 = p2_add(t0, ua); t1 = p2_fma(ua, ua, t1);
            t2 = p2_add(t2, ub); t3 = p2_fma(ub, ub, t3);
        }
        ts[mt][0][0] = t0; ts[mt][0][1] = t1;
        ts[mt][1][0] = t2; ts[mt][1][1] = t3;
    }
    float tr[2][2][2];
    #pragma unroll
    for (int mt = 0; mt < 2; mt++)
        #pragma unroll
        for (int rr = 0; rr < 2; rr++)
            #pragma unroll
            for (int e = 0; e < 2; e++) {
                p2_unpack(ts[mt][rr][e], lo, hi);
                tr[mt][rr][e] = lo + hi;
            }
    #pragma unroll
    for (int mt = 0; mt < 2; mt++)
        #pragma unroll
        for (int rr = 0; rr < 2; rr++)
            #pragma unroll
            for (int e = 0; e < 2; e++)
                tr[mt][rr][e] = qred(tr[mt][rr][e]);
    ull rp[2][2], np[2][2];
    #pragma unroll
    for (int mt = 0; mt < 2; mt++)
        #pragma unroll
        for (int rr = 0; rr < 2; rr++) {
            float m = tr[mt][rr][0] * (1.f / HH);
            float r = rsqrtf(tr[mt][rr][1] * (1.f / HH) - m * m + LN_EPS);
            rp[mt][rr] = p2_pack(r, r);
            np[mt][rr] = p2_pack(-m * r, -m * r);
        }

    // ---- Epilogue Phase B ----
    ull dacc[2][2] = {{0ull, 0ull}, {0ull, 0ull}};
    #pragma unroll
    for (int nt = 0; nt < 8; nt++) {
        int c = nt * 8 + qc * 2;
        ull g2p  = ldg_ull(g2 + c);
        ull be2p = ldg_ull(be2 + c);
        ull w3p  = ldg_ull(W3 + c);
        #pragma unroll
        for (int mt = 0; mt < 2; mt++) {
            float za, zb;
            ull ua = p2_pack(acc[mt][nt][0], acc[mt][nt][1]);
            ull z1 = p2_fma(p2_fma(ua, rp[mt][0], np[mt][0]), g2p, be2p);
            p2_unpack(z1, za, zb);
            dacc[mt][0] = p2_fma(p2_pack(fmaxf(za, 0.f), fmaxf(zb, 0.f)), w3p, dacc[mt][0]);
            ull ub = p2_pack(acc[mt][nt][2], acc[mt][nt][3]);
            ull z2 = p2_fma(p2_fma(ub, rp[mt][1], np[mt][1]), g2p, be2p);
            p2_unpack(z2, za, zb);
            dacc[mt][1] = p2_fma(p2_pack(fmaxf(za, 0.f), fmaxf(zb, 0.f)), w3p, dacc[mt][1]);
        }
    }
    float dv[2][2];
    #pragma unroll
    for (int mt = 0; mt < 2; mt++)
        #pragma unroll
        for (int rr = 0; rr < 2; rr++) {
            p2_unpack(dacc[mt][rr], lo, hi);
            dv[mt][rr] = lo + hi;
        }
    dv[0][0] = qred(dv[0][0]); dv[0][1] = qred(dv[0][1]);
    dv[1][0] = qred(dv[1][0]); dv[1][1] = qred(dv[1][1]);
    if (qc == 0) {
        float b3v = b3[0];
        #pragma unroll
        for (int mt = 0; mt < 2; mt++) {
            int i = i0 + mt;
            out[i * NN + j1]     = 1.f / (1.f + __expf(-(dv[mt][0] + b3v)));
            out[i * NN + j1 + 8] = 1.f / (1.f + __expf(-(dv[mt][1] + b3v)));
        }
    }
}

// ---------------- launch ----------------
extern "C" void kernel_launch(void* const* d_in, const int* in_sizes, int n_in,
                              void* d_out, int out_size) {
    const float* X   = (const float*)d_in[0];
    const float* W1  = (const float*)d_in[1];
    const float* b1  = (const float*)d_in[2];
    const float* g1  = (const float*)d_in[3];
    const float* be1 = (const float*)d_in[4];
    const float* W2  = (const float*)d_in[5];
    const float* b2  = (const float*)d_in[6];
    const float* g2  = (const float*)d_in[7];
    const float* be2 = (const float*)d_in[8];
    const float* W3  = (const float*)d_in[9];
    const float* b3  = (const float*)d_in[10];
    float* out = (float*)d_out;

    prep_all<<<65, 256>>>(X, W1, b1, W2);
    dot_kernel<<<dim3(16, 16), 128>>>();
    dim3 grid(NN / 16, NN / 8);
    pair_kernel<<<grid, 128>>>(g1, be1, b2, g2, be2, W3, b3, out);
}